// round 7
// baseline (speedup 1.0000x reference)
#include <cuda_runtime.h>
#include <cuda_bf16.h>
#include <math.h>
#include <stdint.h>

#define T_TOK 4096
#define H_DIM 1024
#define F_DIM 2816
#define N_EXP 8
#define EPS_V 1e-5f
#define MP_MAX 9216

// smem row pitch (bytes) for 32 bf16 + 16B pad -> conflict-free ldmatrix
#define PITCH 80
#define TILE_B 10240                 // 128 rows * 80B
#define STG   (4 * TILE_B)           // Ah, Al, Bh, Bl per stage = 40960
#define SMEM_TOT (2 * STG)           // 81920 -> 2 CTAs/SM

// ---------------- PTX helpers (sm_80-family, valid on plain sm_103) ---------
__device__ __forceinline__ uint32_t s2u(const void* p) {
    uint32_t a;
    asm("{ .reg .u64 t; cvta.to.shared.u64 t, %1; cvt.u32.u64 %0, t; }" : "=r"(a) : "l"(p));
    return a;
}
__device__ __forceinline__ void ldsm4(uint32_t* r, uint32_t a) {
    asm volatile("ldmatrix.sync.aligned.m8n8.x4.shared.b16 {%0,%1,%2,%3}, [%4];"
        : "=r"(r[0]), "=r"(r[1]), "=r"(r[2]), "=r"(r[3]) : "r"(a));
}
__device__ __forceinline__ void mma16816(float* d, const uint32_t* a, uint32_t b0, uint32_t b1) {
    asm volatile("mma.sync.aligned.m16n8k16.row.col.f32.bf16.bf16.f32 "
        "{%0,%1,%2,%3}, {%4,%5,%6,%7}, {%8,%9}, {%0,%1,%2,%3};"
        : "+f"(d[0]), "+f"(d[1]), "+f"(d[2]), "+f"(d[3])
        : "r"(a[0]), "r"(a[1]), "r"(a[2]), "r"(a[3]), "r"(b0), "r"(b1));
}
__device__ __forceinline__ void cp16(uint32_t s, const void* g) {
    asm volatile("{ .reg .u64 gg; cvta.to.global.u64 gg, %1; "
                 "cp.async.cg.shared.global [%0], [gg], 16; }"
                 :: "r"(s), "l"(g) : "memory");
}
#define CP_COMMIT() asm volatile("cp.async.commit_group;" ::: "memory")
#define CP_WAIT1()  asm volatile("cp.async.wait_group 1;" ::: "memory")

// ---------------- scratch (device globals) ----------------
__device__ __nv_bfloat16 g_x_hi[T_TOK * H_DIM];       // token-indexed split acts
__device__ __nv_bfloat16 g_x_lo[T_TOK * H_DIM];
__device__ __nv_bfloat16 g_h_hi[(size_t)MP_MAX * F_DIM];
__device__ __nv_bfloat16 g_h_lo[(size_t)MP_MAX * F_DIM];
__device__ __nv_bfloat16 g_wg_hi[(size_t)N_EXP * F_DIM * H_DIM];
__device__ __nv_bfloat16 g_wg_lo[(size_t)N_EXP * F_DIM * H_DIM];
__device__ __nv_bfloat16 g_wu_hi[(size_t)N_EXP * F_DIM * H_DIM];
__device__ __nv_bfloat16 g_wu_lo[(size_t)N_EXP * F_DIM * H_DIM];
__device__ __nv_bfloat16 g_wd_hi[(size_t)N_EXP * H_DIM * F_DIM];
__device__ __nv_bfloat16 g_wd_lo[(size_t)N_EXP * H_DIM * F_DIM];
__device__ int   g_tok[MP_MAX];
__device__ float g_scale[MP_MAX];
__device__ int   g_te[T_TOK * 2];
__device__ float g_tp[T_TOK * 2];
__device__ int   g_cnt[N_EXP];
__device__ int   g_offp[N_EXP + 1];

// ---------------- kernel 1: rmsnorm + router + bf16 split ----------------
// Router logits via coalesced float2 reads of rw (4 lanes cover a 32B row).
__global__ __launch_bounds__(256)
void k_rms_router(const float* __restrict__ hs,
                  const float* __restrict__ lnw,
                  const float* __restrict__ rw)
{
    int t = blockIdx.x;
    int tid = threadIdx.x;
    int lane = tid & 31, wid = tid >> 5;

    __shared__ float s_x[H_DIM];
    __shared__ float swr[8];
    __shared__ float s_inv;
    __shared__ float sl[8][N_EXP];

    const float4 v = ((const float4*)(hs + (size_t)t * H_DIM))[tid];
    float ss = v.x*v.x + v.y*v.y + v.z*v.z + v.w*v.w;
    #pragma unroll
    for (int o = 16; o; o >>= 1) ss += __shfl_xor_sync(0xffffffffu, ss, o);
    if (lane == 0) swr[wid] = ss;
    __syncthreads();
    if (tid == 0) {
        float s = 0.f;
        #pragma unroll
        for (int i = 0; i < 8; i++) s += swr[i];
        s_inv = rsqrtf(s / (float)H_DIM + EPS_V);
    }
    __syncthreads();
    float inv = s_inv;

    const float4 w = ((const float4*)lnw)[tid];
    float xv[4];
    xv[0] = v.x * inv * w.x;  xv[1] = v.y * inv * w.y;
    xv[2] = v.z * inv * w.z;  xv[3] = v.w * inv * w.w;

    __nv_bfloat16 hi[4], lo[4];
    #pragma unroll
    for (int j = 0; j < 4; j++) {
        s_x[tid * 4 + j] = xv[j];
        hi[j] = __float2bfloat16(xv[j]);
        lo[j] = __float2bfloat16(xv[j] - __bfloat162float(hi[j]));
    }
    ((uint2*)(g_x_hi + (size_t)t * H_DIM))[tid] = *(uint2*)hi;
    ((uint2*)(g_x_lo + (size_t)t * H_DIM))[tid] = *(uint2*)lo;
    __syncthreads();

    // router phase: warp wid handles i in [wid*128, wid*128+128)
    // lane: c = lane&3 -> expert pair (2c, 2c+1); r = lane>>2 -> row offset
    {
        const int c = lane & 3, r = lane >> 2;
        const float2* rw2 = (const float2*)rw;
        float2 p = make_float2(0.f, 0.f);
        int ibase = wid * 128 + r;
        #pragma unroll
        for (int k = 0; k < 16; k++) {
            int i = ibase + k * 8;
            float2 w2 = rw2[i * 4 + c];
            float xs = s_x[i];
            p.x += xs * w2.x;
            p.y += xs * w2.y;
        }
        #pragma unroll
        for (int o = 16; o >= 4; o >>= 1) {
            p.x += __shfl_xor_sync(0xffffffffu, p.x, o);
            p.y += __shfl_xor_sync(0xffffffffu, p.y, o);
        }
        if (lane < 4) {
            sl[wid][2 * c]     = p.x;
            sl[wid][2 * c + 1] = p.y;
        }
    }
    __syncthreads();

    if (tid == 0) {
        float l[N_EXP];
        #pragma unroll
        for (int e = 0; e < N_EXP; e++) {
            float s = 0.f;
            #pragma unroll
            for (int w2 = 0; w2 < 8; w2++) s += sl[w2][e];
            l[e] = s;
        }
        float m = l[0];
        #pragma unroll
        for (int e = 1; e < N_EXP; e++) m = fmaxf(m, l[e]);
        float den = 0.f, pr[N_EXP];
        #pragma unroll
        for (int e = 0; e < N_EXP; e++) { pr[e] = expf(l[e] - m); den += pr[e]; }
        float rden = 1.f / den;
        #pragma unroll
        for (int e = 0; e < N_EXP; e++) pr[e] *= rden;

        int i1 = 0;
        #pragma unroll
        for (int e = 1; e < N_EXP; e++) if (pr[e] > pr[i1]) i1 = e;
        int i2 = (i1 == 0) ? 1 : 0;
        #pragma unroll
        for (int e = 0; e < N_EXP; e++) if (e != i1 && pr[e] > pr[i2]) i2 = e;

        g_te[t * 2 + 0] = i1;  g_tp[t * 2 + 0] = pr[i1];
        g_te[t * 2 + 1] = i2;  g_tp[t * 2 + 1] = pr[i2];
        atomicAdd(&g_cnt[i1], 1);
        atomicAdd(&g_cnt[i2], 1);
    }
}

// ---------------- kernel 2: ALL weight transposes + bf16 splits --------------
// z: 0..7 wg experts, 8..15 wu, 16..23 wd. Early-exit guards for dim mismatch.
__global__ __launch_bounds__(256)
void k_tsplit_all(const float* __restrict__ wg,
                  const float* __restrict__ wu,
                  const float* __restrict__ wd)
{
    int z = blockIdx.z;
    const float* src;
    __nv_bfloat16 *dhi, *dlo;
    int R, C, e;
    if (z < 8)       { src = wg; dhi = g_wg_hi; dlo = g_wg_lo; R = H_DIM; C = F_DIM; e = z; }
    else if (z < 16) { src = wu; dhi = g_wu_hi; dlo = g_wu_lo; R = H_DIM; C = F_DIM; e = z - 8; }
    else             { src = wd; dhi = g_wd_hi; dlo = g_wd_lo; R = F_DIM; C = H_DIM; e = z - 16; }

    int c0 = blockIdx.x * 32, r0 = blockIdx.y * 64;
    if (c0 >= C || r0 >= R) return;

    __shared__ float t[64][33];
    const float* s = src + (size_t)e * R * C;
    size_t dbase = (size_t)e * R * C;
    int tx = threadIdx.x, ty = threadIdx.y;
    #pragma unroll
    for (int i = 0; i < 8; i++) {
        int r = ty + i * 8;
        t[r][tx] = s[(size_t)(r0 + r) * C + c0 + tx];
    }
    __syncthreads();
    #pragma unroll
    for (int i = 0; i < 4; i++) {
        int c = ty + i * 8;
        float v0 = t[2 * tx][c];
        float v1 = t[2 * tx + 1][c];
        __nv_bfloat16 h0 = __float2bfloat16(v0);
        __nv_bfloat16 h1 = __float2bfloat16(v1);
        __nv_bfloat16 l0 = __float2bfloat16(v0 - __bfloat162float(h0));
        __nv_bfloat16 l1 = __float2bfloat16(v1 - __bfloat162float(h1));
        uint32_t uh = (uint32_t)__bfloat16_as_ushort(h0) | ((uint32_t)__bfloat16_as_ushort(h1) << 16);
        uint32_t ul = (uint32_t)__bfloat16_as_ushort(l0) | ((uint32_t)__bfloat16_as_ushort(l1) << 16);
        size_t o = dbase + (size_t)(c0 + c) * R + r0 + 2 * tx;
        *(uint32_t*)(dhi + o) = uh;
        *(uint32_t*)(dlo + o) = ul;
    }
}

// ---------------- kernel 3: offsets + scatter (single block) -----------------
__global__ __launch_bounds__(256)
void k_offscatter()
{
    __shared__ int s_fill[N_EXP];
    int tid = threadIdx.x;
    if (tid == 0) {
        int acc = 0;
        #pragma unroll
        for (int e = 0; e < N_EXP; e++) {
            g_offp[e]  = acc;
            s_fill[e]  = acc;
            acc += (g_cnt[e] + 127) & ~127;
        }
        g_offp[N_EXP] = acc;
    }
    __syncthreads();
    for (int t = tid; t < T_TOK; t += 256) {
        #pragma unroll
        for (int k = 0; k < 2; k++) {
            int e = g_te[t * 2 + k];
            int r = atomicAdd(&s_fill[e], 1);
            g_tok[r]   = t;
            g_scale[r] = g_tp[t * 2 + k];
        }
    }
}

// ======================= GEMM1: gate/up + SiLU (mma.sync) ====================
__global__ __launch_bounds__(256)
void k_gemm1_mma()
{
    extern __shared__ char smem[];
    const uint32_t sb = s2u(smem);
    const int tid = threadIdx.x, lane = tid & 31, wid = tid >> 5;

    const int Mp = g_offp[N_EXP];
    const int m0 = blockIdx.y * 128;
    if (m0 >= Mp) return;
    const int n0 = blockIdx.x * 64;          // logical col base (gate/up interleave)
    int e = 0;
    #pragma unroll
    for (int i = 1; i < N_EXP; i++) if (m0 >= g_offp[i]) e = i;

    __shared__ int s_tok[128];
    if (tid < 128) {
        int tok = g_tok[m0 + tid];
        s_tok[tid] = (tok >= 0) ? tok : 0;
    }
    __syncthreads();

    const int lr = tid >> 2;
    const int ls = tid & 3;
    const int NC = H_DIM / 32;

    auto load_chunk = [&](int c, int stg) {
        int kc = c * 32;
        uint32_t base = sb + stg * STG;
        uint32_t ah = base, al = base + TILE_B, bh = base + 2 * TILE_B, bl = base + 3 * TILE_B;
        #pragma unroll
        for (int i = 0; i < 2; i++) {
            int row = lr + 64 * i;
            size_t go = (size_t)s_tok[row] * H_DIM + kc + ls * 8;
            cp16(ah + row * PITCH + ls * 16, g_x_hi + go);
            cp16(al + row * PITCH + ls * 16, g_x_lo + go);
        }
        #pragma unroll
        for (int i = 0; i < 2; i++) {
            int rn = lr + 64 * i;
            int col = n0 + (rn >> 1);
            size_t go = ((size_t)e * F_DIM + col) * H_DIM + kc + ls * 8;
            const __nv_bfloat16* Wh = (rn & 1) ? g_wu_hi : g_wg_hi;
            const __nv_bfloat16* Wl = (rn & 1) ? g_wu_lo : g_wg_lo;
            cp16(bh + rn * PITCH + ls * 16, Wh + go);
            cp16(bl + rn * PITCH + ls * 16, Wl + go);
        }
    };

    load_chunk(0, 0); CP_COMMIT();
    load_chunk(1, 1); CP_COMMIT();

    const int warp_m = (wid & 1) * 64;
    const int warp_n = (wid >> 1) * 32;

    float acc[4][4][4];
    #pragma unroll
    for (int i = 0; i < 4; i++)
        #pragma unroll
        for (int j = 0; j < 4; j++)
            #pragma unroll
            for (int k = 0; k < 4; k++) acc[i][j][k] = 0.f;

    const int quad = lane >> 3, l7 = lane & 7;
    const int a_row = warp_m + (quad & 1) * 8 + l7;
    const int b_row = warp_n + (quad & 1) * 8 + l7;
    const int k_off = (quad >> 1) * 16;

    for (int c = 0; c < NC; c++) {
        CP_WAIT1();
        __syncthreads();
        uint32_t base = sb + (c & 1) * STG;
        uint32_t ah = base, al = base + TILE_B, bh = base + 2 * TILE_B, bl = base + 3 * TILE_B;
        #pragma unroll
        for (int ks = 0; ks < 2; ks++) {
            uint32_t aH[4][4], aL[4][4], bH[2][4], bL[2][4];
            #pragma unroll
            for (int mi = 0; mi < 4; mi++) {
                uint32_t ro = (a_row + mi * 16) * PITCH + ks * 32 + k_off;
                ldsm4(aH[mi], ah + ro);
                ldsm4(aL[mi], al + ro);
            }
            #pragma unroll
            for (int bj = 0; bj < 2; bj++) {
                uint32_t ro = (b_row + bj * 16) * PITCH + ks * 32 + k_off;
                ldsm4(bH[bj], bh + ro);
                ldsm4(bL[bj], bl + ro);
            }
            #pragma unroll
            for (int mi = 0; mi < 4; mi++)
                #pragma unroll
                for (int nj = 0; nj < 4; nj++) {
                    const uint32_t* fh = bH[nj >> 1];
                    const uint32_t* fl = bL[nj >> 1];
                    int s = nj & 1;
                    mma16816(acc[mi][nj], aH[mi], fh[s], fh[s + 2]);
                    mma16816(acc[mi][nj], aH[mi], fl[s], fl[s + 2]);
                    mma16816(acc[mi][nj], aL[mi], fh[s], fh[s + 2]);
                }
        }
        __syncthreads();
        if (c + 2 < NC) load_chunk(c + 2, c & 1);
        CP_COMMIT();
    }

    const int rbase = m0 + warp_m + (lane >> 2);
    const int cbase = n0 + (warp_n >> 1) + (lane & 3);
    #pragma unroll
    for (int mi = 0; mi < 4; mi++) {
        size_t r0 = (size_t)(rbase + mi * 16) * F_DIM;
        size_t r1 = r0 + 8 * F_DIM;
        #pragma unroll
        for (int nj = 0; nj < 4; nj++) {
            int L = cbase + nj * 4;
            float g0 = acc[mi][nj][0], u0 = acc[mi][nj][1];
            float g1 = acc[mi][nj][2], u1 = acc[mi][nj][3];
            float h0 = (g0 / (1.f + expf(-g0))) * u0;
            float h1 = (g1 / (1.f + expf(-g1))) * u1;
            __nv_bfloat16 h0h = __float2bfloat16(h0);
            __nv_bfloat16 h1h = __float2bfloat16(h1);
            g_h_hi[r0 + L] = h0h;
            g_h_hi[r1 + L] = h1h;
            g_h_lo[r0 + L] = __float2bfloat16(h0 - __bfloat162float(h0h));
            g_h_lo[r1 + L] = __float2bfloat16(h1 - __bfloat162float(h1h));
        }
    }
}

// ======================= GEMM2: down proj + combine (mma.sync) ===============
__global__ __launch_bounds__(256)
void k_gemm2_mma(float* __restrict__ out)
{
    extern __shared__ char smem[];
    const uint32_t sb = s2u(smem);
    const int tid = threadIdx.x, lane = tid & 31, wid = tid >> 5;

    const int Mp = g_offp[N_EXP];
    const int m0 = blockIdx.y * 128;
    if (m0 >= Mp) return;
    const int n0 = blockIdx.x * 128;
    int e = 0;
    #pragma unroll
    for (int i = 1; i < N_EXP; i++) if (m0 >= g_offp[i]) e = i;

    const int lr = tid >> 2;
    const int ls = tid & 3;
    const int NC = F_DIM / 32;

    auto load_chunk = [&](int c, int stg) {
        int kc = c * 32;
        uint32_t base = sb + stg * STG;
        uint32_t ah = base, al = base + TILE_B, bh = base + 2 * TILE_B, bl = base + 3 * TILE_B;
        #pragma unroll
        for (int i = 0; i < 2; i++) {
            int row = lr + 64 * i;
            size_t go = (size_t)(m0 + row) * F_DIM + kc + ls * 8;
            cp16(ah + row * PITCH + ls * 16, g_h_hi + go);
            cp16(al + row * PITCH + ls * 16, g_h_lo + go);
        }
        #pragma unroll
        for (int i = 0; i < 2; i++) {
            int rn = lr + 64 * i;
            size_t go = ((size_t)e * H_DIM + n0 + rn) * F_DIM + kc + ls * 8;
            cp16(bh + rn * PITCH + ls * 16, g_wd_hi + go);
            cp16(bl + rn * PITCH + ls * 16, g_wd_lo + go);
        }
    };

    load_chunk(0, 0); CP_COMMIT();
    load_chunk(1, 1); CP_COMMIT();

    const int warp_m = (wid & 1) * 64;
    const int warp_n = (wid >> 1) * 32;

    float acc[4][4][4];
    #pragma unroll
    for (int i = 0; i < 4; i++)
        #pragma unroll
        for (int j = 0; j < 4; j++)
            #pragma unroll
            for (int k = 0; k < 4; k++) acc[i][j][k] = 0.f;

    const int quad = lane >> 3, l7 = lane & 7;
    const int a_row = warp_m + (quad & 1) * 8 + l7;
    const int b_row = warp_n + (quad & 1) * 8 + l7;
    const int k_off = (quad >> 1) * 16;

    for (int c = 0; c < NC; c++) {
        CP_WAIT1();
        __syncthreads();
        uint32_t base = sb + (c & 1) * STG;
        uint32_t ah = base, al = base + TILE_B, bh = base + 2 * TILE_B, bl = base + 3 * TILE_B;
        #pragma unroll
        for (int ks = 0; ks < 2; ks++) {
            uint32_t aH[4][4], aL[4][4], bH[2][4], bL[2][4];
            #pragma unroll
            for (int mi = 0; mi < 4; mi++) {
                uint32_t ro = (a_row + mi * 16) * PITCH + ks * 32 + k_off;
                ldsm4(aH[mi], ah + ro);
                ldsm4(aL[mi], al + ro);
            }
            #pragma unroll
            for (int bj = 0; bj < 2; bj++) {
                uint32_t ro = (b_row + bj * 16) * PITCH + ks * 32 + k_off;
                ldsm4(bH[bj], bh + ro);
                ldsm4(bL[bj], bl + ro);
            }
            #pragma unroll
            for (int mi = 0; mi < 4; mi++)
                #pragma unroll
                for (int nj = 0; nj < 4; nj++) {
                    const uint32_t* fh = bH[nj >> 1];
                    const uint32_t* fl = bL[nj >> 1];
                    int s = nj & 1;
                    mma16816(acc[mi][nj], aH[mi], fh[s], fh[s + 2]);
                    mma16816(acc[mi][nj], aH[mi], fl[s], fl[s + 2]);
                    mma16816(acc[mi][nj], aL[mi], fh[s], fh[s + 2]);
                }
        }
        __syncthreads();
        if (c + 2 < NC) load_chunk(c + 2, c & 1);
        CP_COMMIT();
    }

    const int rbase = m0 + warp_m + (lane >> 2);
    const int cbase = n0 + warp_n + (lane & 3) * 2;
    #pragma unroll
    for (int mi = 0; mi < 4; mi++) {
        int r0 = rbase + mi * 16;
        int r1 = r0 + 8;
        int tok0 = g_tok[r0], tok1 = g_tok[r1];
        float sc0 = (tok0 >= 0) ? g_scale[r0] : 0.f;
        float sc1 = (tok1 >= 0) ? g_scale[r1] : 0.f;
        #pragma unroll
        for (int nj = 0; nj < 4; nj++) {
            int col = cbase + nj * 8;
            if (tok0 >= 0) {
                float* p0 = out + (size_t)tok0 * H_DIM + col;
                atomicAdd(p0,     acc[mi][nj][0] * sc0);
                atomicAdd(p0 + 1, acc[mi][nj][1] * sc0);
            }
            if (tok1 >= 0) {
                float* p1 = out + (size_t)tok1 * H_DIM + col;
                atomicAdd(p1,     acc[mi][nj][2] * sc1);
                atomicAdd(p1 + 1, acc[mi][nj][3] * sc1);
            }
        }
    }
}

// ---------------- launch ----------------
extern "C" void kernel_launch(void* const* d_in, const int* in_sizes, int n_in,
                              void* d_out, int out_size)
{
    const float* hs  = (const float*)d_in[0];
    const float* lnw = (const float*)d_in[1];
    const float* rw  = (const float*)d_in[2];
    const float* wg  = (const float*)d_in[3];
    const float* wu  = (const float*)d_in[4];
    const float* wd  = (const float*)d_in[5];
    float* out = (float*)d_out;

    cudaFuncSetAttribute(k_gemm1_mma, cudaFuncAttributeMaxDynamicSharedMemorySize, SMEM_TOT);
    cudaFuncSetAttribute(k_gemm2_mma, cudaFuncAttributeMaxDynamicSharedMemorySize, SMEM_TOT);

    void *p_cnt = nullptr, *p_tok = nullptr;
    cudaGetSymbolAddress(&p_cnt, g_cnt);
    cudaGetSymbolAddress(&p_tok, g_tok);

    cudaMemsetAsync(p_cnt, 0, N_EXP * sizeof(int));
    cudaMemsetAsync(p_tok, 0xFF, MP_MAX * sizeof(int));
    cudaMemsetAsync(out, 0, (size_t)out_size * sizeof(float));

    // launch 1: rmsnorm + router (+ act split)
    k_rms_router<<<T_TOK, 256>>>(hs, lnw, rw);

    // launch 2: all weight transposes + splits
    dim3 tb(32, 8);
    dim3 tg(F_DIM / 32, F_DIM / 64, 24);   // (88, 44, 24), guarded early-exit
    k_tsplit_all<<<tg, tb>>>(wg, wu, wd);

    // launch 3: offsets + scatter
    k_offscatter<<<1, 256>>>();

    // launch 4 (ncu capture slot): GEMM1
    dim3 g1(F_DIM / 64, MP_MAX / 128);   // (44, 72)
    k_gemm1_mma<<<g1, 256, SMEM_TOT>>>();

    // launch 5: GEMM2
    dim3 g2(H_DIM / 128, MP_MAX / 128);  // (8, 72)
    k_gemm2_mma<<<g2, 256, SMEM_TOT>>>(out);
}

// round 8
// speedup vs baseline: 1.1630x; 1.1630x over previous
#include <cuda_runtime.h>
#include <cuda_bf16.h>
#include <math.h>
#include <stdint.h>

#define T_TOK 4096
#define H_DIM 1024
#define F_DIM 2816
#define N_EXP 8
#define EPS_V 1e-5f
#define MP_MAX 9216

// swizzled smem: 64B rows (32 bf16), seg' = seg ^ ((row>>1)&3)
#define TILE_B 8192                  // 128 rows * 64B
#define STG   (4 * TILE_B)           // Ah, Al, Bh, Bl per stage = 32768
#define SMEM_TOT (3 * STG)           // 98304 -> 2 CTAs/SM

// ---------------- PTX helpers (sm_80-family, valid on plain sm_103) ---------
__device__ __forceinline__ uint32_t s2u(const void* p) {
    uint32_t a;
    asm("{ .reg .u64 t; cvta.to.shared.u64 t, %1; cvt.u32.u64 %0, t; }" : "=r"(a) : "l"(p));
    return a;
}
__device__ __forceinline__ void ldsm4(uint32_t* r, uint32_t a) {
    asm volatile("ldmatrix.sync.aligned.m8n8.x4.shared.b16 {%0,%1,%2,%3}, [%4];"
        : "=r"(r[0]), "=r"(r[1]), "=r"(r[2]), "=r"(r[3]) : "r"(a));
}
__device__ __forceinline__ void mma16816(float* d, const uint32_t* a, uint32_t b0, uint32_t b1) {
    asm volatile("mma.sync.aligned.m16n8k16.row.col.f32.bf16.bf16.f32 "
        "{%0,%1,%2,%3}, {%4,%5,%6,%7}, {%8,%9}, {%0,%1,%2,%3};"
        : "+f"(d[0]), "+f"(d[1]), "+f"(d[2]), "+f"(d[3])
        : "r"(a[0]), "r"(a[1]), "r"(a[2]), "r"(a[3]), "r"(b0), "r"(b1));
}
__device__ __forceinline__ void cp16(uint32_t s, const void* g) {
    asm volatile("{ .reg .u64 gg; cvta.to.global.u64 gg, %1; "
                 "cp.async.cg.shared.global [%0], [gg], 16; }"
                 :: "r"(s), "l"(g) : "memory");
}
#define CP_COMMIT() asm volatile("cp.async.commit_group;" ::: "memory")
#define CP_WAIT1()  asm volatile("cp.async.wait_group 1;" ::: "memory")
#define CP_WAIT0()  asm volatile("cp.async.wait_group 0;" ::: "memory")

// ---------------- scratch (device globals) ----------------
__device__ __nv_bfloat16 g_x_hi[T_TOK * H_DIM];
__device__ __nv_bfloat16 g_x_lo[T_TOK * H_DIM];
__device__ __nv_bfloat16 g_h_hi[(size_t)MP_MAX * F_DIM];
__device__ __nv_bfloat16 g_h_lo[(size_t)MP_MAX * F_DIM];
__device__ __nv_bfloat16 g_wg_hi[(size_t)N_EXP * F_DIM * H_DIM];
__device__ __nv_bfloat16 g_wg_lo[(size_t)N_EXP * F_DIM * H_DIM];
__device__ __nv_bfloat16 g_wu_hi[(size_t)N_EXP * F_DIM * H_DIM];
__device__ __nv_bfloat16 g_wu_lo[(size_t)N_EXP * F_DIM * H_DIM];
__device__ __nv_bfloat16 g_wd_hi[(size_t)N_EXP * H_DIM * F_DIM];
__device__ __nv_bfloat16 g_wd_lo[(size_t)N_EXP * H_DIM * F_DIM];
__device__ int   g_tok[MP_MAX];
__device__ float g_scale[MP_MAX];
__device__ int   g_te[T_TOK * 2];
__device__ float g_tp[T_TOK * 2];
__device__ int   g_cnt[N_EXP];
__device__ int   g_offp[N_EXP + 1];

// ---------------- kernel 1: rmsnorm + router + bf16 split ----------------
__global__ __launch_bounds__(256)
void k_rms_router(const float* __restrict__ hs,
                  const float* __restrict__ lnw,
                  const float* __restrict__ rw)
{
    int t = blockIdx.x;
    int tid = threadIdx.x;
    int lane = tid & 31, wid = tid >> 5;

    __shared__ float s_x[H_DIM];
    __shared__ float swr[8];
    __shared__ float s_inv;
    __shared__ float sl[8][N_EXP];

    const float4 v = ((const float4*)(hs + (size_t)t * H_DIM))[tid];
    float ss = v.x*v.x + v.y*v.y + v.z*v.z + v.w*v.w;
    #pragma unroll
    for (int o = 16; o; o >>= 1) ss += __shfl_xor_sync(0xffffffffu, ss, o);
    if (lane == 0) swr[wid] = ss;
    __syncthreads();
    if (tid == 0) {
        float s = 0.f;
        #pragma unroll
        for (int i = 0; i < 8; i++) s += swr[i];
        s_inv = rsqrtf(s / (float)H_DIM + EPS_V);
    }
    __syncthreads();
    float inv = s_inv;

    const float4 w = ((const float4*)lnw)[tid];
    float xv[4];
    xv[0] = v.x * inv * w.x;  xv[1] = v.y * inv * w.y;
    xv[2] = v.z * inv * w.z;  xv[3] = v.w * inv * w.w;

    __nv_bfloat16 hi[4], lo[4];
    #pragma unroll
    for (int j = 0; j < 4; j++) {
        s_x[tid * 4 + j] = xv[j];
        hi[j] = __float2bfloat16(xv[j]);
        lo[j] = __float2bfloat16(xv[j] - __bfloat162float(hi[j]));
    }
    ((uint2*)(g_x_hi + (size_t)t * H_DIM))[tid] = *(uint2*)hi;
    ((uint2*)(g_x_lo + (size_t)t * H_DIM))[tid] = *(uint2*)lo;
    __syncthreads();

    {
        const int c = lane & 3, r = lane >> 2;
        const float2* rw2 = (const float2*)rw;
        float2 p = make_float2(0.f, 0.f);
        int ibase = wid * 128 + r;
        #pragma unroll
        for (int k = 0; k < 16; k++) {
            int i = ibase + k * 8;
            float2 w2 = rw2[i * 4 + c];
            float xs = s_x[i];
            p.x += xs * w2.x;
            p.y += xs * w2.y;
        }
        #pragma unroll
        for (int o = 16; o >= 4; o >>= 1) {
            p.x += __shfl_xor_sync(0xffffffffu, p.x, o);
            p.y += __shfl_xor_sync(0xffffffffu, p.y, o);
        }
        if (lane < 4) {
            sl[wid][2 * c]     = p.x;
            sl[wid][2 * c + 1] = p.y;
        }
    }
    __syncthreads();

    if (tid == 0) {
        float l[N_EXP];
        #pragma unroll
        for (int e = 0; e < N_EXP; e++) {
            float s = 0.f;
            #pragma unroll
            for (int w2 = 0; w2 < 8; w2++) s += sl[w2][e];
            l[e] = s;
        }
        float m = l[0];
        #pragma unroll
        for (int e = 1; e < N_EXP; e++) m = fmaxf(m, l[e]);
        float den = 0.f, pr[N_EXP];
        #pragma unroll
        for (int e = 0; e < N_EXP; e++) { pr[e] = expf(l[e] - m); den += pr[e]; }
        float rden = 1.f / den;
        #pragma unroll
        for (int e = 0; e < N_EXP; e++) pr[e] *= rden;

        int i1 = 0;
        #pragma unroll
        for (int e = 1; e < N_EXP; e++) if (pr[e] > pr[i1]) i1 = e;
        int i2 = (i1 == 0) ? 1 : 0;
        #pragma unroll
        for (int e = 0; e < N_EXP; e++) if (e != i1 && pr[e] > pr[i2]) i2 = e;

        g_te[t * 2 + 0] = i1;  g_tp[t * 2 + 0] = pr[i1];
        g_te[t * 2 + 1] = i2;  g_tp[t * 2 + 1] = pr[i2];
        atomicAdd(&g_cnt[i1], 1);
        atomicAdd(&g_cnt[i2], 1);
    }
}

// ---------------- kernel 2: ALL weight transposes + bf16 splits --------------
__global__ __launch_bounds__(256)
void k_tsplit_all(const float* __restrict__ wg,
                  const float* __restrict__ wu,
                  const float* __restrict__ wd)
{
    int z = blockIdx.z;
    const float* src;
    __nv_bfloat16 *dhi, *dlo;
    int R, C, e;
    if (z < 8)       { src = wg; dhi = g_wg_hi; dlo = g_wg_lo; R = H_DIM; C = F_DIM; e = z; }
    else if (z < 16) { src = wu; dhi = g_wu_hi; dlo = g_wu_lo; R = H_DIM; C = F_DIM; e = z - 8; }
    else             { src = wd; dhi = g_wd_hi; dlo = g_wd_lo; R = F_DIM; C = H_DIM; e = z - 16; }

    int c0 = blockIdx.x * 32, r0 = blockIdx.y * 64;
    if (c0 >= C || r0 >= R) return;

    __shared__ float t[64][33];
    const float* s = src + (size_t)e * R * C;
    size_t dbase = (size_t)e * R * C;
    int tx = threadIdx.x, ty = threadIdx.y;
    #pragma unroll
    for (int i = 0; i < 8; i++) {
        int r = ty + i * 8;
        t[r][tx] = s[(size_t)(r0 + r) * C + c0 + tx];
    }
    __syncthreads();
    #pragma unroll
    for (int i = 0; i < 4; i++) {
        int c = ty + i * 8;
        float v0 = t[2 * tx][c];
        float v1 = t[2 * tx + 1][c];
        __nv_bfloat16 h0 = __float2bfloat16(v0);
        __nv_bfloat16 h1 = __float2bfloat16(v1);
        __nv_bfloat16 l0 = __float2bfloat16(v0 - __bfloat162float(h0));
        __nv_bfloat16 l1 = __float2bfloat16(v1 - __bfloat162float(h1));
        uint32_t uh = (uint32_t)__bfloat16_as_ushort(h0) | ((uint32_t)__bfloat16_as_ushort(h1) << 16);
        uint32_t ul = (uint32_t)__bfloat16_as_ushort(l0) | ((uint32_t)__bfloat16_as_ushort(l1) << 16);
        size_t o = dbase + (size_t)(c0 + c) * R + r0 + 2 * tx;
        *(uint32_t*)(dhi + o) = uh;
        *(uint32_t*)(dlo + o) = ul;
    }
}

// ---------------- kernel 3: offsets + scatter (single block) -----------------
__global__ __launch_bounds__(256)
void k_offscatter()
{
    __shared__ int s_fill[N_EXP];
    int tid = threadIdx.x;
    if (tid == 0) {
        int acc = 0;
        #pragma unroll
        for (int e = 0; e < N_EXP; e++) {
            g_offp[e]  = acc;
            s_fill[e]  = acc;
            acc += (g_cnt[e] + 127) & ~127;
        }
        g_offp[N_EXP] = acc;
    }
    __syncthreads();
    for (int t = tid; t < T_TOK; t += 256) {
        #pragma unroll
        for (int k = 0; k < 2; k++) {
            int e = g_te[t * 2 + k];
            int r = atomicAdd(&s_fill[e], 1);
            g_tok[r]   = t;
            g_scale[r] = g_tp[t * 2 + k];
        }
    }
}

// ======================= GEMM1: gate/up + SiLU (mma.sync) ====================
// Swizzled smem (64B rows), 3-stage cp.async pipeline, ONE sync per chunk.
__global__ __launch_bounds__(256, 2)
void k_gemm1_mma()
{
    extern __shared__ char smem[];
    const uint32_t sb = s2u(smem);
    const int tid = threadIdx.x, lane = tid & 31, wid = tid >> 5;

    const int Mp = g_offp[N_EXP];
    const int m0 = blockIdx.y * 128;
    if (m0 >= Mp) return;
    const int n0 = blockIdx.x * 64;
    int e = 0;
    #pragma unroll
    for (int i = 1; i < N_EXP; i++) if (m0 >= g_offp[i]) e = i;

    __shared__ int s_tok[128];
    if (tid < 128) {
        int tok = g_tok[m0 + tid];
        s_tok[tid] = (tok >= 0) ? tok : 0;
    }
    __syncthreads();

    const int lr = tid >> 2;                  // smem row 0..63 (+64)
    const int ls = tid & 3;                   // 16B segment
    const int NC = H_DIM / 32;                // 32 chunks

    auto load_chunk = [&](int c, int stg) {
        int kc = c * 32;
        uint32_t base = sb + stg * STG;
        uint32_t ah = base, al = base + TILE_B, bh = base + 2 * TILE_B, bl = base + 3 * TILE_B;
        #pragma unroll
        for (int i = 0; i < 2; i++) {
            int row = lr + 64 * i;
            uint32_t so = row * 64 + ((ls ^ ((row >> 1) & 3)) << 4);
            size_t go = (size_t)s_tok[row] * H_DIM + kc + ls * 8;
            cp16(ah + so, g_x_hi + go);
            cp16(al + so, g_x_lo + go);
        }
        #pragma unroll
        for (int i = 0; i < 2; i++) {
            int rn = lr + 64 * i;
            uint32_t so = rn * 64 + ((ls ^ ((rn >> 1) & 3)) << 4);
            int col = n0 + (rn >> 1);
            size_t go = ((size_t)e * F_DIM + col) * H_DIM + kc + ls * 8;
            const __nv_bfloat16* Wh = (rn & 1) ? g_wu_hi : g_wg_hi;
            const __nv_bfloat16* Wl = (rn & 1) ? g_wu_lo : g_wg_lo;
            cp16(bh + so, Wh + go);
            cp16(bl + so, Wl + go);
        }
    };

    load_chunk(0, 0); CP_COMMIT();
    load_chunk(1, 1); CP_COMMIT();

    const int warp_m = (wid & 1) * 64;
    const int warp_n = (wid >> 1) * 32;

    float acc[4][4][4];
    #pragma unroll
    for (int i = 0; i < 4; i++)
        #pragma unroll
        for (int j = 0; j < 4; j++)
            #pragma unroll
            for (int k = 0; k < 4; k++) acc[i][j][k] = 0.f;

    const int quad = lane >> 3, l7 = lane & 7;
    const int a_row = warp_m + (quad & 1) * 8 + l7;
    const int b_row = warp_n + (quad & 1) * 8 + l7;
    const int kq = quad >> 1;                 // 16B seg within k (0/1)
    const int a_swz = (a_row >> 1) & 3;
    const int b_swz = (b_row >> 1) & 3;

    for (int c = 0; c < NC; c++) {
        if (c + 1 < NC) { CP_WAIT1(); } else { CP_WAIT0(); }
        __syncthreads();
        if (c + 2 < NC) { load_chunk(c + 2, (c + 2) % 3); CP_COMMIT(); }

        uint32_t base = sb + (c % 3) * STG;
        uint32_t ah = base, al = base + TILE_B, bh = base + 2 * TILE_B, bl = base + 3 * TILE_B;
        #pragma unroll
        for (int ks = 0; ks < 2; ks++) {
            const uint32_t a_seg = (uint32_t)(((ks * 2 + kq) ^ a_swz) << 4);
            const uint32_t b_seg = (uint32_t)(((ks * 2 + kq) ^ b_swz) << 4);
            uint32_t aH[4][4], aL[4][4], bH[2][4], bL[2][4];
            #pragma unroll
            for (int mi = 0; mi < 4; mi++) {
                uint32_t ro = (a_row + mi * 16) * 64 + a_seg;
                ldsm4(aH[mi], ah + ro);
                ldsm4(aL[mi], al + ro);
            }
            #pragma unroll
            for (int bj = 0; bj < 2; bj++) {
                uint32_t ro = (b_row + bj * 16) * 64 + b_seg;
                ldsm4(bH[bj], bh + ro);
                ldsm4(bL[bj], bl + ro);
            }
            #pragma unroll
            for (int mi = 0; mi < 4; mi++)
                #pragma unroll
                for (int nj = 0; nj < 4; nj++) {
                    const uint32_t* fh = bH[nj >> 1];
                    const uint32_t* fl = bL[nj >> 1];
                    int s = nj & 1;
                    mma16816(acc[mi][nj], aH[mi], fh[s], fh[s + 2]);
                    mma16816(acc[mi][nj], aH[mi], fl[s], fl[s + 2]);
                    mma16816(acc[mi][nj], aL[mi], fh[s], fh[s + 2]);
                }
        }
    }

    const int rbase = m0 + warp_m + (lane >> 2);
    const int cbase = n0 + (warp_n >> 1) + (lane & 3);
    #pragma unroll
    for (int mi = 0; mi < 4; mi++) {
        size_t r0 = (size_t)(rbase + mi * 16) * F_DIM;
        size_t r1 = r0 + 8 * F_DIM;
        #pragma unroll
        for (int nj = 0; nj < 4; nj++) {
            int L = cbase + nj * 4;
            float g0 = acc[mi][nj][0], u0 = acc[mi][nj][1];
            float g1 = acc[mi][nj][2], u1 = acc[mi][nj][3];
            float h0 = (g0 / (1.f + expf(-g0))) * u0;
            float h1 = (g1 / (1.f + expf(-g1))) * u1;
            __nv_bfloat16 h0h = __float2bfloat16(h0);
            __nv_bfloat16 h1h = __float2bfloat16(h1);
            g_h_hi[r0 + L] = h0h;
            g_h_hi[r1 + L] = h1h;
            g_h_lo[r0 + L] = __float2bfloat16(h0 - __bfloat162float(h0h));
            g_h_lo[r1 + L] = __float2bfloat16(h1 - __bfloat162float(h1h));
        }
    }
}

// ======================= GEMM2: down proj + combine (mma.sync) ===============
__global__ __launch_bounds__(256, 2)
void k_gemm2_mma(float* __restrict__ out)
{
    extern __shared__ char smem[];
    const uint32_t sb = s2u(smem);
    const int tid = threadIdx.x, lane = tid & 31, wid = tid >> 5;

    const int Mp = g_offp[N_EXP];
    const int m0 = blockIdx.y * 128;
    if (m0 >= Mp) return;
    const int n0 = blockIdx.x * 128;
    int e = 0;
    #pragma unroll
    for (int i = 1; i < N_EXP; i++) if (m0 >= g_offp[i]) e = i;

    const int lr = tid >> 2;
    const int ls = tid & 3;
    const int NC = F_DIM / 32;                // 88 chunks

    auto load_chunk = [&](int c, int stg) {
        int kc = c * 32;
        uint32_t base = sb + stg * STG;
        uint32_t ah = base, al = base + TILE_B, bh = base + 2 * TILE_B, bl = base + 3 * TILE_B;
        #pragma unroll
        for (int i = 0; i < 2; i++) {
            int row = lr + 64 * i;
            uint32_t so = row * 64 + ((ls ^ ((row >> 1) & 3)) << 4);
            size_t go = (size_t)(m0 + row) * F_DIM + kc + ls * 8;
            cp16(ah + so, g_h_hi + go);
            cp16(al + so, g_h_lo + go);
        }
        #pragma unroll
        for (int i = 0; i < 2; i++) {
            int rn = lr + 64 * i;
            uint32_t so = rn * 64 + ((ls ^ ((rn >> 1) & 3)) << 4);
            size_t go = ((size_t)e * H_DIM + n0 + rn) * F_DIM + kc + ls * 8;
            cp16(bh + so, g_wd_hi + go);
            cp16(bl + so, g_wd_lo + go);
        }
    };

    load_chunk(0, 0); CP_COMMIT();
    load_chunk(1, 1); CP_COMMIT();

    const int warp_m = (wid & 1) * 64;
    const int warp_n = (wid >> 1) * 32;

    float acc[4][4][4];
    #pragma unroll
    for (int i = 0; i < 4; i++)
        #pragma unroll
        for (int j = 0; j < 4; j++)
            #pragma unroll
            for (int k = 0; k < 4; k++) acc[i][j][k] = 0.f;

    const int quad = lane >> 3, l7 = lane & 7;
    const int a_row = warp_m + (quad & 1) * 8 + l7;
    const int b_row = warp_n + (quad & 1) * 8 + l7;
    const int kq = quad >> 1;
    const int a_swz = (a_row >> 1) & 3;
    const int b_swz = (b_row >> 1) & 3;

    for (int c = 0; c < NC; c++) {
        if (c + 1 < NC) { CP_WAIT1(); } else { CP_WAIT0(); }
        __syncthreads();
        if (c + 2 < NC) { load_chunk(c + 2, (c + 2) % 3); CP_COMMIT(); }

        uint32_t base = sb + (c % 3) * STG;
        uint32_t ah = base, al = base + TILE_B, bh = base + 2 * TILE_B, bl = base + 3 * TILE_B;
        #pragma unroll
        for (int ks = 0; ks < 2; ks++) {
            const uint32_t a_seg = (uint32_t)(((ks * 2 + kq) ^ a_swz) << 4);
            const uint32_t b_seg = (uint32_t)(((ks * 2 + kq) ^ b_swz) << 4);
            uint32_t aH[4][4], aL[4][4], bH[2][4], bL[2][4];
            #pragma unroll
            for (int mi = 0; mi < 4; mi++) {
                uint32_t ro = (a_row + mi * 16) * 64 + a_seg;
                ldsm4(aH[mi], ah + ro);
                ldsm4(aL[mi], al + ro);
            }
            #pragma unroll
            for (int bj = 0; bj < 2; bj++) {
                uint32_t ro = (b_row + bj * 16) * 64 + b_seg;
                ldsm4(bH[bj], bh + ro);
                ldsm4(bL[bj], bl + ro);
            }
            #pragma unroll
            for (int mi = 0; mi < 4; mi++)
                #pragma unroll
                for (int nj = 0; nj < 4; nj++) {
                    const uint32_t* fh = bH[nj >> 1];
                    const uint32_t* fl = bL[nj >> 1];
                    int s = nj & 1;
                    mma16816(acc[mi][nj], aH[mi], fh[s], fh[s + 2]);
                    mma16816(acc[mi][nj], aH[mi], fl[s], fl[s + 2]);
                    mma16816(acc[mi][nj], aL[mi], fh[s], fh[s + 2]);
                }
        }
    }

    const int rbase = m0 + warp_m + (lane >> 2);
    const int cbase = n0 + warp_n + (lane & 3) * 2;
    #pragma unroll
    for (int mi = 0; mi < 4; mi++) {
        int r0 = rbase + mi * 16;
        int r1 = r0 + 8;
        int tok0 = g_tok[r0], tok1 = g_tok[r1];
        float sc0 = (tok0 >= 0) ? g_scale[r0] : 0.f;
        float sc1 = (tok1 >= 0) ? g_scale[r1] : 0.f;
        #pragma unroll
        for (int nj = 0; nj < 4; nj++) {
            int col = cbase + nj * 8;
            if (tok0 >= 0) {
                float* p0 = out + (size_t)tok0 * H_DIM + col;
                atomicAdd(p0,     acc[mi][nj][0] * sc0);
                atomicAdd(p0 + 1, acc[mi][nj][1] * sc0);
            }
            if (tok1 >= 0) {
                float* p1 = out + (size_t)tok1 * H_DIM + col;
                atomicAdd(p1,     acc[mi][nj][2] * sc1);
                atomicAdd(p1 + 1, acc[mi][nj][3] * sc1);
            }
        }
    }
}

// ---------------- launch ----------------
extern "C" void kernel_launch(void* const* d_in, const int* in_sizes, int n_in,
                              void* d_out, int out_size)
{
    const float* hs  = (const float*)d_in[0];
    const float* lnw = (const float*)d_in[1];
    const float* rw  = (const float*)d_in[2];
    const float* wg  = (const float*)d_in[3];
    const float* wu  = (const float*)d_in[4];
    const float* wd  = (const float*)d_in[5];
    float* out = (float*)d_out;

    cudaFuncSetAttribute(k_gemm1_mma, cudaFuncAttributeMaxDynamicSharedMemorySize, SMEM_TOT);
    cudaFuncSetAttribute(k_gemm2_mma, cudaFuncAttributeMaxDynamicSharedMemorySize, SMEM_TOT);

    void *p_cnt = nullptr, *p_tok = nullptr;
    cudaGetSymbolAddress(&p_cnt, g_cnt);
    cudaGetSymbolAddress(&p_tok, g_tok);

    cudaMemsetAsync(p_cnt, 0, N_EXP * sizeof(int));
    cudaMemsetAsync(p_tok, 0xFF, MP_MAX * sizeof(int));
    cudaMemsetAsync(out, 0, (size_t)out_size * sizeof(float));

    // launch 1: rmsnorm + router (+ act split)
    k_rms_router<<<T_TOK, 256>>>(hs, lnw, rw);

    // launch 2: all weight transposes + splits
    dim3 tb(32, 8);
    dim3 tg(F_DIM / 32, F_DIM / 64, 24);
    k_tsplit_all<<<tg, tb>>>(wg, wu, wd);

    // launch 3: offsets + scatter
    k_offscatter<<<1, 256>>>();

    // launch 4 (ncu capture slot): GEMM1
    dim3 g1(F_DIM / 64, MP_MAX / 128);   // (44, 72)
    k_gemm1_mma<<<g1, 256, SMEM_TOT>>>();

    // launch 5: GEMM2
    dim3 g2(H_DIM / 128, MP_MAX / 128);  // (8, 72)
    k_gemm2_mma<<<g2, 256, SMEM_TOT>>>(out);
}